// round 9
// baseline (speedup 1.0000x reference)
#include <cuda_runtime.h>

// Problem constants
#define BD 4          // batch
#define SS 2048       // sequence
#define DD 1024       // model dim

// GEMM tiling
constexpr int BM = 128, BN = 128, BK = 16;
constexpr int TM = 8,  TN = 8;          // per-thread microtile
constexpr int NTHREADS = 256;           // 16x16 thread grid

// Scratch (device globals: module-load allocation, legal under _HX_ENFORCE)
__device__ float g_q[(size_t)BD * SS * DD];              // 33.5 MB
__device__ float g_k[(size_t)BD * SS * DD];              // 33.5 MB
__device__ float g_v[(size_t)BD * SS * DD];              // 33.5 MB
__device__ float g_p[(size_t)BD * SS * SS];              // 64 MB scores/probs

// ---------------------------------------------------------------------------
// Double-buffered SGEMM core: C_tile(128x128) += A(MxK, row-major) * op(B)
//   TRANSB = true : B is [N,K] row-major (NT gemm, dot along contiguous K)
//   TRANSB = false: B is [K,N] row-major (NN gemm)
// All dims are multiples of the tile sizes for every call here.
// ---------------------------------------------------------------------------
template <bool TRANSB>
__device__ __forceinline__ void gemm_tile(const float* __restrict__ A, int lda,
                                          const float* __restrict__ Bm, int ldb,
                                          int K, float (&acc)[TM][TN]) {
    __shared__ float As[2][BK][BM + 4];   // +4 pad kills transpose-store conflicts
    __shared__ float Bs[2][BK][BN + 4];

    const int tid = threadIdx.x;
    const int tx  = tid & 15;             // 0..15 -> N direction
    const int ty  = tid >> 4;             // 0..15 -> M direction
    const int m0  = blockIdx.y * BM;
    const int n0  = blockIdx.x * BN;

    // K-contiguous loader indices (A always; B when TRANSB)
    const int lrow = tid >> 2;            // 0..63
    const int lkc  = (tid & 3) * 4;       // 0,4,8,12
    // NN loader indices for B
    const int krow = tid >> 5;            // 0..7
    const int c4   = (tid & 31) * 4;      // 0..124

    // ---- fetch helpers (global -> registers) ----
    auto fetchA = [&](int k0, float4 (&r)[2]) {
        #pragma unroll
        for (int j = 0; j < 2; ++j)
            r[j] = *(const float4*)&A[(size_t)(m0 + lrow + j * 64) * lda + k0 + lkc];
    };
    auto fetchB = [&](int k0, float4 (&r)[2]) {
        if (TRANSB) {
            #pragma unroll
            for (int j = 0; j < 2; ++j)
                r[j] = *(const float4*)&Bm[(size_t)(n0 + lrow + j * 64) * ldb + k0 + lkc];
        } else {
            #pragma unroll
            for (int j = 0; j < 2; ++j)
                r[j] = *(const float4*)&Bm[(size_t)(k0 + krow + j * 8) * ldb + n0 + c4];
        }
    };
    // ---- store helpers (registers -> smem buffer) ----
    auto putA = [&](int buf, const float4 (&r)[2]) {
        #pragma unroll
        for (int j = 0; j < 2; ++j) {
            const int row = lrow + j * 64;
            As[buf][lkc + 0][row] = r[j].x;
            As[buf][lkc + 1][row] = r[j].y;
            As[buf][lkc + 2][row] = r[j].z;
            As[buf][lkc + 3][row] = r[j].w;
        }
    };
    auto putB = [&](int buf, const float4 (&r)[2]) {
        if (TRANSB) {
            #pragma unroll
            for (int j = 0; j < 2; ++j) {
                const int row = lrow + j * 64;
                Bs[buf][lkc + 0][row] = r[j].x;
                Bs[buf][lkc + 1][row] = r[j].y;
                Bs[buf][lkc + 2][row] = r[j].z;
                Bs[buf][lkc + 3][row] = r[j].w;
            }
        } else {
            #pragma unroll
            for (int j = 0; j < 2; ++j) {
                const int kr = krow + j * 8;
                Bs[buf][kr][c4 + 0] = r[j].x;
                Bs[buf][kr][c4 + 1] = r[j].y;
                Bs[buf][kr][c4 + 2] = r[j].z;
                Bs[buf][kr][c4 + 3] = r[j].w;
            }
        }
    };

    // ---- prologue: tile 0 into buffer 0 ----
    {
        float4 ra[2], rb[2];
        fetchA(0, ra); fetchB(0, rb);
        putA(0, ra);   putB(0, rb);
    }
    __syncthreads();

    int buf = 0;
    for (int k0 = 0; k0 < K; k0 += BK) {
        float4 pa[2], pb[2];
        const bool has_next = (k0 + BK < K);
        if (has_next) { fetchA(k0 + BK, pa); fetchB(k0 + BK, pb); }

        // ---- 16 K-steps of 8x8 FFMA on current buffer ----
        #pragma unroll
        for (int kk = 0; kk < BK; ++kk) {
            float ra[TM], rb[TN];
            #pragma unroll
            for (int i = 0; i < TM; ++i) ra[i] = As[buf][kk][ty * TM + i];
            #pragma unroll
            for (int j = 0; j < TN; ++j) rb[j] = Bs[buf][kk][tx * TN + j];
            #pragma unroll
            for (int i = 0; i < TM; ++i)
                #pragma unroll
                for (int j = 0; j < TN; ++j)
                    acc[i][j] += ra[i] * rb[j];
        }

        if (has_next) {
            putA(buf ^ 1, pa); putB(buf ^ 1, pb);
            __syncthreads();
            buf ^= 1;
        }
    }
}

__device__ __forceinline__ void store_acc(float* __restrict__ C, int ldc, float alpha,
                                          const float (&acc)[TM][TN]) {
    const int tx = threadIdx.x & 15;
    const int ty = threadIdx.x >> 4;
    const int m0 = blockIdx.y * BM + ty * TM;
    const int n0 = blockIdx.x * BN + tx * TN;
    #pragma unroll
    for (int i = 0; i < TM; ++i) {
        float4 v0 = make_float4(acc[i][0] * alpha, acc[i][1] * alpha,
                                acc[i][2] * alpha, acc[i][3] * alpha);
        float4 v1 = make_float4(acc[i][4] * alpha, acc[i][5] * alpha,
                                acc[i][6] * alpha, acc[i][7] * alpha);
        *(float4*)&C[(size_t)(m0 + i) * ldc + n0]     = v0;
        *(float4*)&C[(size_t)(m0 + i) * ldc + n0 + 4] = v1;
    }
}

// ---------------------------------------------------------------------------
// Kernel 1: QKV = x @ W^T, routed into g_q / g_k / g_v
//   x: [B*S, D] row-major, W: [3D, D] row-major (NT)
// ---------------------------------------------------------------------------
__global__ void __launch_bounds__(NTHREADS, 2)
qkv_kernel(const float* __restrict__ x, const float* __restrict__ W) {
    float acc[TM][TN] = {};
    gemm_tile<true>(x, DD, W, DD, DD, acc);

    // BN=128 divides DD: the whole block's columns fall in exactly one of q/k/v
    const int nblk = blockIdx.x * BN;
    float* dst;
    int    nbias;
    if (nblk < DD)          { dst = g_q; nbias = 0;      }
    else if (nblk < 2 * DD) { dst = g_k; nbias = DD;     }
    else                    { dst = g_v; nbias = 2 * DD; }
    // store_acc recomputes the global column n0; shift base so effective col = n0-nbias
    store_acc(dst - nbias, DD, 1.0f, acc);
}

// ---------------------------------------------------------------------------
// Kernel 2: per-batch scores  P_b = (Q_b @ K_b^T) / sqrt(D)
// ---------------------------------------------------------------------------
__global__ void __launch_bounds__(NTHREADS, 2)
score_kernel() {
    const int b = blockIdx.z;
    const float* Aq = g_q + (size_t)b * SS * DD;
    const float* Bk = g_k + (size_t)b * SS * DD;
    float acc[TM][TN] = {};
    gemm_tile<true>(Aq, DD, Bk, DD, DD, acc);
    store_acc(g_p + (size_t)b * SS * SS, SS, 0.03125f /* 1/sqrt(1024) */, acc);
}

// ---------------------------------------------------------------------------
// Kernel 3: row softmax over g_p rows (length 2048), in place
// ---------------------------------------------------------------------------
__global__ void softmax_kernel() {
    __shared__ float red[8];
    __shared__ float bcast;
    float* p = g_p + (size_t)blockIdx.x * SS;
    const int tid = threadIdx.x;

    float4 a = ((float4*)p)[tid];
    float4 c = ((float4*)p)[tid + 256];

    // max
    float m = fmaxf(fmaxf(fmaxf(a.x, a.y), fmaxf(a.z, a.w)),
                    fmaxf(fmaxf(c.x, c.y), fmaxf(c.z, c.w)));
    #pragma unroll
    for (int o = 16; o > 0; o >>= 1) m = fmaxf(m, __shfl_xor_sync(~0u, m, o));
    if ((tid & 31) == 0) red[tid >> 5] = m;
    __syncthreads();
    if (tid < 32) {
        float t = (tid < 8) ? red[tid] : -3.4e38f;
        #pragma unroll
        for (int o = 4; o > 0; o >>= 1) t = fmaxf(t, __shfl_xor_sync(~0u, t, o));
        if (tid == 0) bcast = t;
    }
    __syncthreads();
    m = bcast;

    // exp + sum
    a.x = __expf(a.x - m); a.y = __expf(a.y - m);
    a.z = __expf(a.z - m); a.w = __expf(a.w - m);
    c.x = __expf(c.x - m); c.y = __expf(c.y - m);
    c.z = __expf(c.z - m); c.w = __expf(c.w - m);
    float s = (a.x + a.y) + (a.z + a.w) + (c.x + c.y) + (c.z + c.w);
    #pragma unroll
    for (int o = 16; o > 0; o >>= 1) s += __shfl_xor_sync(~0u, s, o);
    __syncthreads();
    if ((tid & 31) == 0) red[tid >> 5] = s;
    __syncthreads();
    if (tid < 32) {
        float t = (tid < 8) ? red[tid] : 0.0f;
        #pragma unroll
        for (int o = 4; o > 0; o >>= 1) t += __shfl_xor_sync(~0u, t, o);
        if (tid == 0) bcast = t;
    }
    __syncthreads();
    const float inv = 1.0f / bcast;

    a.x *= inv; a.y *= inv; a.z *= inv; a.w *= inv;
    c.x *= inv; c.y *= inv; c.z *= inv; c.w *= inv;
    ((float4*)p)[tid]       = a;
    ((float4*)p)[tid + 256] = c;
}

// ---------------------------------------------------------------------------
// Kernel 4: per-batch  Y_b = P_b @ V_b   (NN: V is [S, D] row-major)
// ---------------------------------------------------------------------------
__global__ void __launch_bounds__(NTHREADS, 2)
out_kernel(float* __restrict__ out) {
    const int b = blockIdx.z;
    const float* Ap = g_p + (size_t)b * SS * SS;
    const float* Bv = g_v + (size_t)b * SS * DD;
    float acc[TM][TN] = {};
    gemm_tile<false>(Ap, SS, Bv, DD, SS, acc);
    store_acc(out + (size_t)b * SS * DD, DD, 1.0f, acc);
}

// ---------------------------------------------------------------------------
extern "C" void kernel_launch(void* const* d_in, const int* in_sizes, int n_in,
                              void* d_out, int out_size) {
    const float* x = (const float*)d_in[0];   // [4, 2048, 1024]
    const float* W = (const float*)d_in[1];   // [3072, 1024]
    float* out = (float*)d_out;               // [4, 2048, 1024]
    (void)in_sizes; (void)n_in; (void)out_size;

    qkv_kernel  <<<dim3(3 * DD / BN, (BD * SS) / BM), NTHREADS>>>(x, W);
    score_kernel<<<dim3(SS / BN, SS / BM, BD),        NTHREADS>>>();
    softmax_kernel<<<BD * SS, NTHREADS>>>();
    out_kernel  <<<dim3(DD / BN, SS / BM, BD),        NTHREADS>>>(out);
}

// round 11
// speedup vs baseline: 2.2111x; 2.2111x over previous
#include <cuda_runtime.h>
#include <cuda_bf16.h>
#include <cstdint>

#define BD 4
#define SS 2048
#define DDIM 1024

constexpr size_t NX = (size_t)BD * SS * DDIM;    // 8388608
constexpr size_t NW = (size_t)3 * DDIM * DDIM;   // 3145728
constexpr size_t NP = (size_t)BD * SS * SS;      // 16777216

// Scratch: __device__ globals (module-load allocation, legal under _HX_ENFORCE)
__device__ __nv_bfloat16 g_xh[NX], g_xl[NX];
__device__ __nv_bfloat16 g_wh[NW], g_wl[NW];
__device__ __nv_bfloat16 g_qh[NX], g_ql[NX];
__device__ __nv_bfloat16 g_kh[NX], g_kl[NX];
__device__ __nv_bfloat16 g_vh[NX], g_vl[NX];
__device__ __nv_bfloat16 g_vTh[NX], g_vTl[NX];
__device__ float         g_p [NP];
__device__ __nv_bfloat16 g_ph[NP], g_pl[NP];

// ---------------- tiling ----------------
constexpr int CHUNK   = 64;                // K bf16 elems per pipeline chunk
constexpr int TILE_B  = 128 * 128;         // 128 rows x 128B = 16 KB
constexpr int STAGE_B = 4 * TILE_B;        // Ah, Al, Bh, Bl = 64 KB
constexpr int DSMEM   = 2 * STAGE_B;       // 2-stage pipeline = 128 KB

// ---------------- PTX helpers (all base-sm_103 legal) ----------------
__device__ __forceinline__ uint32_t smem_u32(const void* p) {
    uint32_t a;
    asm("{ .reg .u64 t; cvta.to.shared.u64 t, %1; cvt.u32.u64 %0, t; }"
        : "=r"(a) : "l"(p));
    return a;
}
__device__ __forceinline__ void cpasync16(uint32_t dst, const void* src) {
    asm volatile("cp.async.cg.shared.global [%0], [%1], 16;"
                 :: "r"(dst), "l"(src) : "memory");
}
__device__ __forceinline__ void cp_commit() {
    asm volatile("cp.async.commit_group;" ::: "memory");
}
__device__ __forceinline__ void cp_wait1() {
    asm volatile("cp.async.wait_group 1;" ::: "memory");
}
__device__ __forceinline__ uint32_t swz(uint32_t off) {
    return off ^ ((off >> 3) & 0x70);
}

#define LDSM4(r, a) \
    asm volatile("ldmatrix.sync.aligned.m8n8.x4.shared.b16 {%0,%1,%2,%3}, [%4];" \
        : "=r"((r)[0]), "=r"((r)[1]), "=r"((r)[2]), "=r"((r)[3]) : "r"(a))
#define LDSM2(r, a) \
    asm volatile("ldmatrix.sync.aligned.m8n8.x2.shared.b16 {%0,%1}, [%2];" \
        : "=r"((r)[0]), "=r"((r)[1]) : "r"(a))
#define MMA16816(d, a, b) \
    asm volatile("mma.sync.aligned.m16n8k16.row.col.f32.bf16.bf16.f32 " \
        "{%0,%1,%2,%3}, {%4,%5,%6,%7}, {%8,%9}, {%0,%1,%2,%3};" \
        : "+f"((d)[0]), "+f"((d)[1]), "+f"((d)[2]), "+f"((d)[3]) \
        : "r"((a)[0]), "r"((a)[1]), "r"((a)[2]), "r"((a)[3]), \
          "r"((b)[0]), "r"((b)[1]))

// ---------------- chunk loader: 128 rows x 64 bf16 -> SW128 smem, via cp.async ----
__device__ __forceinline__ void issue_tile(uint32_t sbase,
                                           const __nv_bfloat16* __restrict__ src,
                                           int ld, int r0, int c0) {
    const int t   = threadIdx.x;
    const int row = t >> 1, h = t & 1;
    const __nv_bfloat16* g = src + (size_t)(r0 + row) * ld + c0 + h * 32;
    #pragma unroll
    for (int j = 0; j < 4; ++j) {
        uint32_t off = row * 128 + h * 64 + j * 16;
        cpasync16(sbase + swz(off), g + j * 8);
    }
}

// ---------------- shared mainloop ----------------
// acc[im][in][4] = sum over K of A(m0..m0+127, :) * B(n0..n0+127, :)^T  (bf16x3)
// A,B stored K-major ([row][k], k contiguous). Warp wid: wm=(wid&1)*64, wn=(wid>>1)*32.
// Acc element (im,in): rows wm+16*im + lane/4 (+8 for regs 2,3), col wn+8*in+(lane%4)*2.
__device__ void mma_main(const __nv_bfloat16* __restrict__ Ah,
                         const __nv_bfloat16* __restrict__ Al, int lda,
                         const __nv_bfloat16* __restrict__ Bh,
                         const __nv_bfloat16* __restrict__ Bl, int ldb,
                         int m0, int n0, int K, float acc[4][4][4]) {
    extern __shared__ char dsm[];
    const uint32_t sb = smem_u32(dsm);
    const int NC = K / CHUNK;

    auto issue = [&](int c, int s) {
        const uint32_t st = sb + s * STAGE_B;
        const int c0 = c * CHUNK;
        issue_tile(st,              Ah, lda, m0, c0);
        issue_tile(st + TILE_B,     Al, lda, m0, c0);
        issue_tile(st + 2 * TILE_B, Bh, ldb, n0, c0);
        issue_tile(st + 3 * TILE_B, Bl, ldb, n0, c0);
        cp_commit();
    };

    const int lane = threadIdx.x & 31;
    const int wid  = threadIdx.x >> 5;
    const int wm   = (wid & 1) * 64;
    const int wn   = (wid >> 1) * 32;
    const int arow = (lane & 7) + ((lane >> 3) & 1) * 8;  // A ldmatrix row-in-tile16
    const int asel = lane >> 4;                           // A k-unit select
    const int brow = lane & 7;                            // B ldmatrix row
    const int bsel = (lane >> 3) & 1;                     // B k-unit select

    issue(0, 0);
    int buf = 0;
    for (int c = 0; c < NC; ++c) {
        if (c + 1 < NC) issue(c + 1, buf ^ 1); else cp_commit();
        cp_wait1();
        __syncthreads();

        const uint32_t st = sb + buf * STAGE_B;
        #pragma unroll
        for (int ks = 0; ks < 4; ++ks) {
            uint32_t ah[4][4], al[4][4], bh[4][2], bl[4][2];
            #pragma unroll
            for (int im = 0; im < 4; ++im) {
                const int R = wm + 16 * im + arow;
                const uint32_t off = R * 128 + (((ks * 2 + asel) ^ (R & 7)) << 4);
                LDSM4(ah[im], st + off);
                LDSM4(al[im], st + TILE_B + off);
            }
            #pragma unroll
            for (int in = 0; in < 4; ++in) {
                const int R = wn + 8 * in + brow;
                const uint32_t off = R * 128 + (((ks * 2 + bsel) ^ (R & 7)) << 4);
                LDSM2(bh[in], st + 2 * TILE_B + off);
                LDSM2(bl[in], st + 3 * TILE_B + off);
            }
            #pragma unroll
            for (int im = 0; im < 4; ++im)
                #pragma unroll
                for (int in = 0; in < 4; ++in) {
                    MMA16816(acc[im][in], ah[im], bh[in]);
                    MMA16816(acc[im][in], ah[im], bl[in]);
                    MMA16816(acc[im][in], al[im], bh[in]);
                }
        }
        __syncthreads();
        buf ^= 1;
    }
}

// ---------------- GEMM kernels ----------------
__global__ void __launch_bounds__(256)
qkv_mma_kernel() {
    const int m0 = blockIdx.y * 128, n0 = blockIdx.x * 128;
    float acc[4][4][4] = {};
    mma_main(g_xh, g_xl, DDIM, g_wh, g_wl, DDIM, m0, n0, DDIM, acc);

    const int lane = threadIdx.x & 31, wid = threadIdx.x >> 5;
    const int wm = (wid & 1) * 64, wn = (wid >> 1) * 32;
    const int r = lane >> 2, cq = (lane & 3) * 2;
    const int nt = n0 >> 10;                 // 0:q 1:k 2:v
    __nv_bfloat16 *dh, *dl;
    if (nt == 0)      { dh = g_qh; dl = g_ql; }
    else if (nt == 1) { dh = g_kh; dl = g_kl; }
    else              { dh = g_vh; dl = g_vl; }

    #pragma unroll
    for (int im = 0; im < 4; ++im)
        #pragma unroll
        for (int in = 0; in < 4; ++in) {
            const int col = (n0 & 1023) + wn + 8 * in + cq;
            #pragma unroll
            for (int h2 = 0; h2 < 2; ++h2) {
                const float f0 = acc[im][in][2 * h2];
                const float f1 = acc[im][in][2 * h2 + 1];
                const size_t off = (size_t)(m0 + wm + 16 * im + r + 8 * h2) * DDIM + col;
                __nv_bfloat16 b0 = __float2bfloat16(f0), b1 = __float2bfloat16(f1);
                __nv_bfloat16 c0 = __float2bfloat16(f0 - __bfloat162float(b0));
                __nv_bfloat16 c1 = __float2bfloat16(f1 - __bfloat162float(b1));
                *(uint32_t*)(dh + off) =
                    (uint32_t)__bfloat16_as_ushort(b0) | ((uint32_t)__bfloat16_as_ushort(b1) << 16);
                *(uint32_t*)(dl + off) =
                    (uint32_t)__bfloat16_as_ushort(c0) | ((uint32_t)__bfloat16_as_ushort(c1) << 16);
            }
        }
}

__global__ void __launch_bounds__(256)
score_mma_kernel() {
    const int b = blockIdx.z;
    const int m0 = blockIdx.y * 128, n0 = blockIdx.x * 128;
    const size_t bo = (size_t)b * SS * DDIM;
    float acc[4][4][4] = {};
    mma_main(g_qh + bo, g_ql + bo, DDIM, g_kh + bo, g_kl + bo, DDIM, m0, n0, DDIM, acc);

    const int lane = threadIdx.x & 31, wid = threadIdx.x >> 5;
    const int wm = (wid & 1) * 64, wn = (wid >> 1) * 32;
    const int r = lane >> 2, cq = (lane & 3) * 2;
    #pragma unroll
    for (int im = 0; im < 4; ++im)
        #pragma unroll
        for (int in = 0; in < 4; ++in) {
            const int col = n0 + wn + 8 * in + cq;
            #pragma unroll
            for (int h2 = 0; h2 < 2; ++h2) {
                const size_t off =
                    (size_t)(b * SS + m0 + wm + 16 * im + r + 8 * h2) * SS + col;
                *(float2*)(g_p + off) =
                    make_float2(acc[im][in][2 * h2]     * 0.03125f,
                                acc[im][in][2 * h2 + 1] * 0.03125f);
            }
        }
}

__global__ void __launch_bounds__(256)
out_mma_kernel(float* __restrict__ out) {
    const int b = blockIdx.z;
    const int m0 = blockIdx.y * 128, n0 = blockIdx.x * 128;
    const size_t po = (size_t)b * SS * SS;
    const size_t vo = (size_t)b * DDIM * SS;
    float acc[4][4][4] = {};
    mma_main(g_ph + po, g_pl + po, SS, g_vTh + vo, g_vTl + vo, SS, m0, n0, SS, acc);

    const int lane = threadIdx.x & 31, wid = threadIdx.x >> 5;
    const int wm = (wid & 1) * 64, wn = (wid >> 1) * 32;
    const int r = lane >> 2, cq = (lane & 3) * 2;
    #pragma unroll
    for (int im = 0; im < 4; ++im)
        #pragma unroll
        for (int in = 0; in < 4; ++in) {
            const int col = n0 + wn + 8 * in + cq;
            #pragma unroll
            for (int h2 = 0; h2 < 2; ++h2) {
                const size_t off =
                    (size_t)(b * SS + m0 + wm + 16 * im + r + 8 * h2) * DDIM + col;
                *(float2*)(out + off) =
                    make_float2(acc[im][in][2 * h2], acc[im][in][2 * h2 + 1]);
            }
        }
}

// ---------------- fp32 -> (hi, lo) bf16 split ----------------
__global__ void convert_hilo(const float* __restrict__ s,
                             __nv_bfloat16* __restrict__ h,
                             __nv_bfloat16* __restrict__ l) {
    const int i = blockIdx.x * 256 + threadIdx.x;
    float4 v = ((const float4*)s)[i];
    __nv_bfloat16 h0 = __float2bfloat16(v.x), h1 = __float2bfloat16(v.y);
    __nv_bfloat16 h2 = __float2bfloat16(v.z), h3 = __float2bfloat16(v.w);
    __nv_bfloat16 l0 = __float2bfloat16(v.x - __bfloat162float(h0));
    __nv_bfloat16 l1 = __float2bfloat16(v.y - __bfloat162float(h1));
    __nv_bfloat16 l2 = __float2bfloat16(v.z - __bfloat162float(h2));
    __nv_bfloat16 l3 = __float2bfloat16(v.w - __bfloat162float(h3));
    uint2 uh, ul;
    uh.x = (uint32_t)__bfloat16_as_ushort(h0) | ((uint32_t)__bfloat16_as_ushort(h1) << 16);
    uh.y = (uint32_t)__bfloat16_as_ushort(h2) | ((uint32_t)__bfloat16_as_ushort(h3) << 16);
    ul.x = (uint32_t)__bfloat16_as_ushort(l0) | ((uint32_t)__bfloat16_as_ushort(l1) << 16);
    ul.y = (uint32_t)__bfloat16_as_ushort(l2) | ((uint32_t)__bfloat16_as_ushort(l3) << 16);
    ((uint2*)h)[i] = uh;
    ((uint2*)l)[i] = ul;
}

// ---------------- v[b][s][d] -> vT[b][d][s] (bf16) ----------------
__global__ void transpose_v() {
    __shared__ __nv_bfloat16 ts[32][33];
    const int z = blockIdx.z, b = z >> 1;
    const __nv_bfloat16* src = (z & 1) ? g_vl  : g_vh;
    __nv_bfloat16*       dst = (z & 1) ? g_vTl : g_vTh;
    const int s0 = blockIdx.x * 32, d0 = blockIdx.y * 32;
    const int c = threadIdx.x, r = threadIdx.y;
    #pragma unroll
    for (int i = 0; i < 4; ++i) {
        const int rr = r + 8 * i;
        ts[rr][c] = src[(size_t)(b * SS + s0 + rr) * DDIM + d0 + c];
    }
    __syncthreads();
    #pragma unroll
    for (int i = 0; i < 4; ++i) {
        const int rr = r + 8 * i;
        dst[(size_t)(b * DDIM + d0 + rr) * SS + s0 + c] = ts[c][rr];
    }
}

// ---------------- row softmax over g_p rows (len 2048) -> hi/lo bf16 ----------------
__global__ void softmax_kernel() {
    __shared__ float red[8];
    __shared__ float bcast;
    const size_t row = blockIdx.x;
    const float* p = g_p + row * SS;
    const int tid = threadIdx.x;

    float4 a = ((const float4*)p)[tid];
    float4 c = ((const float4*)p)[tid + 256];

    float m = fmaxf(fmaxf(fmaxf(a.x, a.y), fmaxf(a.z, a.w)),
                    fmaxf(fmaxf(c.x, c.y), fmaxf(c.z, c.w)));
    #pragma unroll
    for (int o = 16; o > 0; o >>= 1) m = fmaxf(m, __shfl_xor_sync(~0u, m, o));
    if ((tid & 31) == 0) red[tid >> 5] = m;
    __syncthreads();
    if (tid < 32) {
        float t = (tid < 8) ? red[tid] : -3.4e38f;
        #pragma unroll
        for (int o = 4; o > 0; o >>= 1) t = fmaxf(t, __shfl_xor_sync(~0u, t, o));
        if (tid == 0) bcast = t;
    }
    __syncthreads();
    m = bcast;

    a.x = __expf(a.x - m); a.y = __expf(a.y - m);
    a.z = __expf(a.z - m); a.w = __expf(a.w - m);
    c.x = __expf(c.x - m); c.y = __expf(c.y - m);
    c.z = __expf(c.z - m); c.w = __expf(c.w - m);
    float s = (a.x + a.y) + (a.z + a.w) + (c.x + c.y) + (c.z + c.w);
    #pragma unroll
    for (int o = 16; o > 0; o >>= 1) s += __shfl_xor_sync(~0u, s, o);
    __syncthreads();
    if ((tid & 31) == 0) red[tid >> 5] = s;
    __syncthreads();
    if (tid < 32) {
        float t = (tid < 8) ? red[tid] : 0.0f;
        #pragma unroll
        for (int o = 4; o > 0; o >>= 1) t += __shfl_xor_sync(~0u, t, o);
        if (tid == 0) bcast = t;
    }
    __syncthreads();
    const float inv = 1.0f / bcast;

    a.x *= inv; a.y *= inv; a.z *= inv; a.w *= inv;
    c.x *= inv; c.y *= inv; c.z *= inv; c.w *= inv;

    auto emit = [&](float4 v, size_t col) {
        __nv_bfloat16 h0 = __float2bfloat16(v.x), h1 = __float2bfloat16(v.y);
        __nv_bfloat16 h2 = __float2bfloat16(v.z), h3 = __float2bfloat16(v.w);
        __nv_bfloat16 l0 = __float2bfloat16(v.x - __bfloat162float(h0));
        __nv_bfloat16 l1 = __float2bfloat16(v.y - __bfloat162float(h1));
        __nv_bfloat16 l2 = __float2bfloat16(v.z - __bfloat162float(h2));
        __nv_bfloat16 l3 = __float2bfloat16(v.w - __bfloat162float(h3));
        uint2 uh, ul;
        uh.x = (uint32_t)__bfloat16_as_ushort(h0) | ((uint32_t)__bfloat16_as_ushort(h1) << 16);
        uh.y = (uint32_t)__bfloat16_as_ushort(h2) | ((uint32_t)__bfloat16_as_ushort(h3) << 16);
        ul.x = (uint32_t)__bfloat16_as_ushort(l0) | ((uint32_t)__bfloat16_as_ushort(l1) << 16);
        ul.y = (uint32_t)__bfloat16_as_ushort(l2) | ((uint32_t)__bfloat16_as_ushort(l3) << 16);
        *(uint2*)(g_ph + row * SS + col) = uh;
        *(uint2*)(g_pl + row * SS + col) = ul;
    };
    emit(a, (size_t)tid * 4);
    emit(c, (size_t)tid * 4 + 1024);
}

// ---------------------------------------------------------------------------
extern "C" void kernel_launch(void* const* d_in, const int* in_sizes, int n_in,
                              void* d_out, int out_size) {
    const float* x = (const float*)d_in[0];   // [4, 2048, 1024]
    const float* W = (const float*)d_in[1];   // [3072, 1024]
    float* out = (float*)d_out;               // [4, 2048, 1024]
    (void)in_sizes; (void)n_in; (void)out_size;

    cudaFuncSetAttribute(qkv_mma_kernel,   cudaFuncAttributeMaxDynamicSharedMemorySize, DSMEM);
    cudaFuncSetAttribute(score_mma_kernel, cudaFuncAttributeMaxDynamicSharedMemorySize, DSMEM);
    cudaFuncSetAttribute(out_mma_kernel,   cudaFuncAttributeMaxDynamicSharedMemorySize, DSMEM);

    __nv_bfloat16 *xh, *xl, *wh, *wl;
    cudaGetSymbolAddress((void**)&xh, g_xh);
    cudaGetSymbolAddress((void**)&xl, g_xl);
    cudaGetSymbolAddress((void**)&wh, g_wh);
    cudaGetSymbolAddress((void**)&wl, g_wl);

    convert_hilo<<<(int)(NX / 4 / 256), 256>>>(x, xh, xl);
    convert_hilo<<<(int)(NW / 4 / 256), 256>>>(W, wh, wl);

    qkv_mma_kernel  <<<dim3(3 * DDIM / 128, BD * SS / 128), 256, DSMEM>>>();
    transpose_v     <<<dim3(SS / 32, DDIM / 32, BD * 2), dim3(32, 8)>>>();
    score_mma_kernel<<<dim3(SS / 128, SS / 128, BD), 256, DSMEM>>>();
    softmax_kernel  <<<BD * SS, 256>>>();
    out_mma_kernel  <<<dim3(DDIM / 128, SS / 128, BD), 256, DSMEM>>>(out);
}

// round 13
// speedup vs baseline: 2.2337x; 1.0102x over previous
#include <cuda_runtime.h>
#include <cuda_bf16.h>
#include <cstdint>

#define BD 4
#define SS 2048
#define DDIM 1024

constexpr size_t NX = (size_t)BD * SS * DDIM;    // 8388608
constexpr size_t NW = (size_t)3 * DDIM * DDIM;   // 3145728
constexpr size_t NP = (size_t)BD * SS * SS;      // 16777216

// Scratch: __device__ globals (module-load allocation, legal under _HX_ENFORCE)
__device__ __nv_bfloat16 g_xh[NX], g_xl[NX];
__device__ __nv_bfloat16 g_wh[NW], g_wl[NW];
__device__ __nv_bfloat16 g_qh[NX], g_ql[NX];
__device__ __nv_bfloat16 g_kh[NX], g_kl[NX];
__device__ __nv_bfloat16 g_vh[NX], g_vl[NX];
__device__ __nv_bfloat16 g_vTh[NX], g_vTl[NX];
__device__ float         g_p [NP];
__device__ __nv_bfloat16 g_ph[NP], g_pl[NP];

// ---------------- tiling ----------------
constexpr int CHUNK   = 64;                // K bf16 elems per pipeline chunk
constexpr int TILE_B  = 128 * 128;         // 128 rows x 128B = 16 KB
constexpr int STAGE_B = 4 * TILE_B;        // Ah, Al, Bh, Bl = 64 KB
constexpr int NSTAGE  = 3;                 // 3-stage ring = 192 KB
constexpr int DSMEM   = NSTAGE * STAGE_B;

// ---------------- PTX helpers (all base-sm_103 legal) ----------------
__device__ __forceinline__ uint32_t smem_u32(const void* p) {
    uint32_t a;
    asm("{ .reg .u64 t; cvta.to.shared.u64 t, %1; cvt.u32.u64 %0, t; }"
        : "=r"(a) : "l"(p));
    return a;
}
__device__ __forceinline__ void cpasync16(uint32_t dst, const void* src) {
    asm volatile("cp.async.cg.shared.global [%0], [%1], 16;"
                 :: "r"(dst), "l"(src) : "memory");
}
__device__ __forceinline__ void cp_commit() {
    asm volatile("cp.async.commit_group;" ::: "memory");
}
__device__ __forceinline__ void cp_wait1() {
    asm volatile("cp.async.wait_group 1;" ::: "memory");
}
__device__ __forceinline__ uint32_t swz(uint32_t off) {
    return off ^ ((off >> 3) & 0x70);
}

#define LDSM4(r, a) \
    asm volatile("ldmatrix.sync.aligned.m8n8.x4.shared.b16 {%0,%1,%2,%3}, [%4];" \
        : "=r"((r)[0]), "=r"((r)[1]), "=r"((r)[2]), "=r"((r)[3]) : "r"(a))
#define LDSM2(r, a) \
    asm volatile("ldmatrix.sync.aligned.m8n8.x2.shared.b16 {%0,%1}, [%2];" \
        : "=r"((r)[0]), "=r"((r)[1]) : "r"(a))
#define MMA16816(d, a, b) \
    asm volatile("mma.sync.aligned.m16n8k16.row.col.f32.bf16.bf16.f32 " \
        "{%0,%1,%2,%3}, {%4,%5,%6,%7}, {%8,%9}, {%0,%1,%2,%3};" \
        : "+f"((d)[0]), "+f"((d)[1]), "+f"((d)[2]), "+f"((d)[3]) \
        : "r"((a)[0]), "r"((a)[1]), "r"((a)[2]), "r"((a)[3]), \
          "r"((b)[0]), "r"((b)[1]))

// ---------------- chunk loader: 128 rows x 64 bf16 -> SW128 smem, via cp.async ----
__device__ __forceinline__ void issue_tile(uint32_t sbase,
                                           const __nv_bfloat16* __restrict__ src,
                                           int ld, int r0, int c0) {
    const int t   = threadIdx.x;
    const int row = t >> 1, h = t & 1;
    const __nv_bfloat16* g = src + (size_t)(r0 + row) * ld + c0 + h * 32;
    #pragma unroll
    for (int j = 0; j < 4; ++j) {
        uint32_t off = row * 128 + h * 64 + j * 16;
        cpasync16(sbase + swz(off), g + j * 8);
    }
}

// ---------------- shared mainloop ----------------
// acc[im][in][4] = sum over K of A(m0..m0+127, :) * B(n0..n0+127, :)^T  (bf16x3)
// A,B stored K-major ([row][k], k contiguous). Warp wid: wm=(wid&1)*64, wn=(wid>>1)*32.
// Acc element (im,in): rows wm+16*im + lane/4 (+8 for regs 2,3), col wn+8*in+(lane%4)*2.
__device__ void mma_main(const __nv_bfloat16* __restrict__ Ah,
                         const __nv_bfloat16* __restrict__ Al, int lda,
                         const __nv_bfloat16* __restrict__ Bh,
                         const __nv_bfloat16* __restrict__ Bl, int ldb,
                         int m0, int n0, int K, float acc[4][4][4]) {
    extern __shared__ char dsm[];
    const uint32_t sb = smem_u32(dsm);
    const int NC = K / CHUNK;

    auto issue = [&](int c, int s) {
        const uint32_t st = sb + s * STAGE_B;
        const int c0 = c * CHUNK;
        issue_tile(st,              Ah, lda, m0, c0);
        issue_tile(st + TILE_B,     Al, lda, m0, c0);
        issue_tile(st + 2 * TILE_B, Bh, ldb, n0, c0);
        issue_tile(st + 3 * TILE_B, Bl, ldb, n0, c0);
        cp_commit();
    };

    const int lane = threadIdx.x & 31;
    const int wid  = threadIdx.x >> 5;
    const int wm   = (wid & 1) * 64;
    const int wn   = (wid >> 1) * 32;
    const int arow = (lane & 7) + ((lane >> 3) & 1) * 8;  // A ldmatrix row-in-tile16
    const int asel = lane >> 4;                           // A k-unit select
    const int brow = lane & 7;                            // B ldmatrix row
    const int bsel = (lane >> 3) & 1;                     // B k-unit select

    // prologue: fill 2 of 3 stages
    issue(0, 0);
    if (NC > 1) issue(1, 1); else cp_commit();

    int buf = 0;
    for (int c = 0; c < NC; ++c) {
        cp_wait1();            // chunk c resident (<=1 group still in flight)
        __syncthreads();       // all threads see stage `buf`; stage (c+2)%3 free
        if (c + 2 < NC) issue(c + 2, (c + 2) % NSTAGE); else cp_commit();

        const uint32_t st = sb + buf * STAGE_B;
        #pragma unroll
        for (int ks = 0; ks < 4; ++ks) {
            uint32_t ah[4][4], al[4][4], bh[4][2], bl[4][2];
            #pragma unroll
            for (int im = 0; im < 4; ++im) {
                const int R = wm + 16 * im + arow;
                const uint32_t off = R * 128 + (((ks * 2 + asel) ^ (R & 7)) << 4);
                LDSM4(ah[im], st + off);
                LDSM4(al[im], st + TILE_B + off);
            }
            #pragma unroll
            for (int in = 0; in < 4; ++in) {
                const int R = wn + 8 * in + brow;
                const uint32_t off = R * 128 + (((ks * 2 + bsel) ^ (R & 7)) << 4);
                LDSM2(bh[in], st + 2 * TILE_B + off);
                LDSM2(bl[in], st + 3 * TILE_B + off);
            }
            // term-major ordering: 16 independent accumulators per term, so
            // same-acc reuse distance is 16 MMAs (>= HMMA latency) instead of 1.
            #pragma unroll
            for (int im = 0; im < 4; ++im)
                #pragma unroll
                for (int in = 0; in < 4; ++in)
                    MMA16816(acc[im][in], ah[im], bh[in]);
            #pragma unroll
            for (int im = 0; im < 4; ++im)
                #pragma unroll
                for (int in = 0; in < 4; ++in)
                    MMA16816(acc[im][in], ah[im], bl[in]);
            #pragma unroll
            for (int im = 0; im < 4; ++im)
                #pragma unroll
                for (int in = 0; in < 4; ++in)
                    MMA16816(acc[im][in], al[im], bh[in]);
        }
        buf = (buf + 1 == NSTAGE) ? 0 : buf + 1;
    }
}

// ---------------- GEMM kernels ----------------
__global__ void __launch_bounds__(256)
qkv_mma_kernel() {
    const int m0 = blockIdx.y * 128, n0 = blockIdx.x * 128;
    float acc[4][4][4] = {};
    mma_main(g_xh, g_xl, DDIM, g_wh, g_wl, DDIM, m0, n0, DDIM, acc);

    const int lane = threadIdx.x & 31, wid = threadIdx.x >> 5;
    const int wm = (wid & 1) * 64, wn = (wid >> 1) * 32;
    const int r = lane >> 2, cq = (lane & 3) * 2;
    const int nt = n0 >> 10;                 // 0:q 1:k 2:v
    __nv_bfloat16 *dh, *dl;
    if (nt == 0)      { dh = g_qh; dl = g_ql; }
    else if (nt == 1) { dh = g_kh; dl = g_kl; }
    else              { dh = g_vh; dl = g_vl; }

    #pragma unroll
    for (int im = 0; im < 4; ++im)
        #pragma unroll
        for (int in = 0; in < 4; ++in) {
            const int col = (n0 & 1023) + wn + 8 * in + cq;
            #pragma unroll
            for (int h2 = 0; h2 < 2; ++h2) {
                const float f0 = acc[im][in][2 * h2];
                const float f1 = acc[im][in][2 * h2 + 1];
                const size_t off = (size_t)(m0 + wm + 16 * im + r + 8 * h2) * DDIM + col;
                __nv_bfloat16 b0 = __float2bfloat16(f0), b1 = __float2bfloat16(f1);
                __nv_bfloat16 c0 = __float2bfloat16(f0 - __bfloat162float(b0));
                __nv_bfloat16 c1 = __float2bfloat16(f1 - __bfloat162float(b1));
                *(uint32_t*)(dh + off) =
                    (uint32_t)__bfloat16_as_ushort(b0) | ((uint32_t)__bfloat16_as_ushort(b1) << 16);
                *(uint32_t*)(dl + off) =
                    (uint32_t)__bfloat16_as_ushort(c0) | ((uint32_t)__bfloat16_as_ushort(c1) << 16);
            }
        }
}

__global__ void __launch_bounds__(256)
score_mma_kernel() {
    const int b = blockIdx.z;
    const int m0 = blockIdx.y * 128, n0 = blockIdx.x * 128;
    const size_t bo = (size_t)b * SS * DDIM;
    float acc[4][4][4] = {};
    mma_main(g_qh + bo, g_ql + bo, DDIM, g_kh + bo, g_kl + bo, DDIM, m0, n0, DDIM, acc);

    const int lane = threadIdx.x & 31, wid = threadIdx.x >> 5;
    const int wm = (wid & 1) * 64, wn = (wid >> 1) * 32;
    const int r = lane >> 2, cq = (lane & 3) * 2;
    #pragma unroll
    for (int im = 0; im < 4; ++im)
        #pragma unroll
        for (int in = 0; in < 4; ++in) {
            const int col = n0 + wn + 8 * in + cq;
            #pragma unroll
            for (int h2 = 0; h2 < 2; ++h2) {
                const size_t off =
                    (size_t)(b * SS + m0 + wm + 16 * im + r + 8 * h2) * SS + col;
                *(float2*)(g_p + off) =
                    make_float2(acc[im][in][2 * h2]     * 0.03125f,
                                acc[im][in][2 * h2 + 1] * 0.03125f);
            }
        }
}

__global__ void __launch_bounds__(256)
out_mma_kernel(float* __restrict__ out) {
    const int b = blockIdx.z;
    const int m0 = blockIdx.y * 128, n0 = blockIdx.x * 128;
    const size_t po = (size_t)b * SS * SS;
    const size_t vo = (size_t)b * DDIM * SS;
    float acc[4][4][4] = {};
    mma_main(g_ph + po, g_pl + po, SS, g_vTh + vo, g_vTl + vo, SS, m0, n0, SS, acc);

    const int lane = threadIdx.x & 31, wid = threadIdx.x >> 5;
    const int wm = (wid & 1) * 64, wn = (wid >> 1) * 32;
    const int r = lane >> 2, cq = (lane & 3) * 2;
    #pragma unroll
    for (int im = 0; im < 4; ++im)
        #pragma unroll
        for (int in = 0; in < 4; ++in) {
            const int col = n0 + wn + 8 * in + cq;
            #pragma unroll
            for (int h2 = 0; h2 < 2; ++h2) {
                const size_t off =
                    (size_t)(b * SS + m0 + wm + 16 * im + r + 8 * h2) * DDIM + col;
                *(float2*)(out + off) =
                    make_float2(acc[im][in][2 * h2], acc[im][in][2 * h2 + 1]);
            }
        }
}

// ---------------- fp32 -> (hi, lo) bf16 split ----------------
__global__ void convert_hilo(const float* __restrict__ s,
                             __nv_bfloat16* __restrict__ h,
                             __nv_bfloat16* __restrict__ l) {
    const int i = blockIdx.x * 256 + threadIdx.x;
    float4 v = ((const float4*)s)[i];
    __nv_bfloat16 h0 = __float2bfloat16(v.x), h1 = __float2bfloat16(v.y);
    __nv_bfloat16 h2 = __float2bfloat16(v.z), h3 = __float2bfloat16(v.w);
    __nv_bfloat16 l0 = __float2bfloat16(v.x - __bfloat162float(h0));
    __nv_bfloat16 l1 = __float2bfloat16(v.y - __bfloat162float(h1));
    __nv_bfloat16 l2 = __float2bfloat16(v.z - __bfloat162float(h2));
    __nv_bfloat16 l3 = __float2bfloat16(v.w - __bfloat162float(h3));
    uint2 uh, ul;
    uh.x = (uint32_t)__bfloat16_as_ushort(h0) | ((uint32_t)__bfloat16_as_ushort(h1) << 16);
    uh.y = (uint32_t)__bfloat16_as_ushort(h2) | ((uint32_t)__bfloat16_as_ushort(h3) << 16);
    ul.x = (uint32_t)__bfloat16_as_ushort(l0) | ((uint32_t)__bfloat16_as_ushort(l1) << 16);
    ul.y = (uint32_t)__bfloat16_as_ushort(l2) | ((uint32_t)__bfloat16_as_ushort(l3) << 16);
    ((uint2*)h)[i] = uh;
    ((uint2*)l)[i] = ul;
}

// ---------------- v[b][s][d] -> vT[b][d][s] (bf16) ----------------
__global__ void transpose_v() {
    __shared__ __nv_bfloat16 ts[32][33];
    const int z = blockIdx.z, b = z >> 1;
    const __nv_bfloat16* src = (z & 1) ? g_vl  : g_vh;
    __nv_bfloat16*       dst = (z & 1) ? g_vTl : g_vTh;
    const int s0 = blockIdx.x * 32, d0 = blockIdx.y * 32;
    const int c = threadIdx.x, r = threadIdx.y;
    #pragma unroll
    for (int i = 0; i < 4; ++i) {
        const int rr = r + 8 * i;
        ts[rr][c] = src[(size_t)(b * SS + s0 + rr) * DDIM + d0 + c];
    }
    __syncthreads();
    #pragma unroll
    for (int i = 0; i < 4; ++i) {
        const int rr = r + 8 * i;
        dst[(size_t)(b * DDIM + d0 + rr) * SS + s0 + c] = ts[c][rr];
    }
}

// ---------------- row softmax over g_p rows (len 2048) -> hi/lo bf16 ----------------
__global__ void softmax_kernel() {
    __shared__ float red[8];
    __shared__ float bcast;
    const size_t row = blockIdx.x;
    const float* p = g_p + row * SS;
    const int tid = threadIdx.x;

    float4 a = ((const float4*)p)[tid];
    float4 c = ((const float4*)p)[tid + 256];

    float m = fmaxf(fmaxf(fmaxf(a.x, a.y), fmaxf(a.z, a.w)),
                    fmaxf(fmaxf(c.x, c.y), fmaxf(c.z, c.w)));
    #pragma unroll
    for (int o = 16; o > 0; o >>= 1) m = fmaxf(m, __shfl_xor_sync(~0u, m, o));
    if ((tid & 31) == 0) red[tid >> 5] = m;
    __syncthreads();
    if (tid < 32) {
        float t = (tid < 8) ? red[tid] : -3.4e38f;
        #pragma unroll
        for (int o = 4; o > 0; o >>= 1) t = fmaxf(t, __shfl_xor_sync(~0u, t, o));
        if (tid == 0) bcast = t;
    }
    __syncthreads();
    m = bcast;

    a.x = __expf(a.x - m); a.y = __expf(a.y - m);
    a.z = __expf(a.z - m); a.w = __expf(a.w - m);
    c.x = __expf(c.x - m); c.y = __expf(c.y - m);
    c.z = __expf(c.z - m); c.w = __expf(c.w - m);
    float s = (a.x + a.y) + (a.z + a.w) + (c.x + c.y) + (c.z + c.w);
    #pragma unroll
    for (int o = 16; o > 0; o >>= 1) s += __shfl_xor_sync(~0u, s, o);
    __syncthreads();
    if ((tid & 31) == 0) red[tid >> 5] = s;
    __syncthreads();
    if (tid < 32) {
        float t = (tid < 8) ? red[tid] : 0.0f;
        #pragma unroll
        for (int o = 4; o > 0; o >>= 1) t += __shfl_xor_sync(~0u, t, o);
        if (tid == 0) bcast = t;
    }
    __syncthreads();
    const float inv = 1.0f / bcast;

    a.x *= inv; a.y *= inv; a.z *= inv; a.w *= inv;
    c.x *= inv; c.y *= inv; c.z *= inv; c.w *= inv;

    auto emit = [&](float4 v, size_t col) {
        __nv_bfloat16 h0 = __float2bfloat16(v.x), h1 = __float2bfloat16(v.y);
        __nv_bfloat16 h2 = __float2bfloat16(v.z), h3 = __float2bfloat16(v.w);
        __nv_bfloat16 l0 = __float2bfloat16(v.x - __bfloat162float(h0));
        __nv_bfloat16 l1 = __float2bfloat16(v.y - __bfloat162float(h1));
        __nv_bfloat16 l2 = __float2bfloat16(v.z - __bfloat162float(h2));
        __nv_bfloat16 l3 = __float2bfloat16(v.w - __bfloat162float(h3));
        uint2 uh, ul;
        uh.x = (uint32_t)__bfloat16_as_ushort(h0) | ((uint32_t)__bfloat16_as_ushort(h1) << 16);
        uh.y = (uint32_t)__bfloat16_as_ushort(h2) | ((uint32_t)__bfloat16_as_ushort(h3) << 16);
        ul.x = (uint32_t)__bfloat16_as_ushort(l0) | ((uint32_t)__bfloat16_as_ushort(l1) << 16);
        ul.y = (uint32_t)__bfloat16_as_ushort(l2) | ((uint32_t)__bfloat16_as_ushort(l3) << 16);
        *(uint2*)(g_ph + row * SS + col) = uh;
        *(uint2*)(g_pl + row * SS + col) = ul;
    };
    emit(a, (size_t)tid * 4);
    emit(c, (size_t)tid * 4 + 1024);
}

// ---------------------------------------------------------------------------
extern "C" void kernel_launch(void* const* d_in, const int* in_sizes, int n_in,
                              void* d_out, int out_size) {
    const float* x = (const float*)d_in[0];   // [4, 2048, 1024]
    const float* W = (const float*)d_in[1];   // [3072, 1024]
    float* out = (float*)d_out;               // [4, 2048, 1024]
    (void)in_sizes; (void)n_in; (void)out_size;

    cudaFuncSetAttribute(qkv_mma_kernel,   cudaFuncAttributeMaxDynamicSharedMemorySize, DSMEM);
    cudaFuncSetAttribute(score_mma_kernel, cudaFuncAttributeMaxDynamicSharedMemorySize, DSMEM);
    cudaFuncSetAttribute(out_mma_kernel,   cudaFuncAttributeMaxDynamicSharedMemorySize, DSMEM);

    __nv_bfloat16 *xh, *xl, *wh, *wl;
    cudaGetSymbolAddress((void**)&xh, g_xh);
    cudaGetSymbolAddress((void**)&xl, g_xl);
    cudaGetSymbolAddress((void**)&wh, g_wh);
    cudaGetSymbolAddress((void**)&wl, g_wl);

    convert_hilo<<<(int)(NX / 4 / 256), 256>>>(x, xh, xl);
    convert_hilo<<<(int)(NW / 4 / 256), 256>>>(W, wh, wl);

    qkv_mma_kernel  <<<dim3(3 * DDIM / 128, BD * SS / 128), 256, DSMEM>>>();
    transpose_v     <<<dim3(SS / 32, DDIM / 32, BD * 2), dim3(32, 8)>>>();
    score_mma_kernel<<<dim3(SS / 128, SS / 128, BD), 256, DSMEM>>>();
    softmax_kernel  <<<BD * SS, 256>>>();
    out_mma_kernel  <<<dim3(DDIM / 128, SS / 128, BD), 256, DSMEM>>>(out);
}

// round 14
// speedup vs baseline: 2.6414x; 1.1825x over previous
#include <cuda_runtime.h>
#include <cuda_bf16.h>
#include <cstdint>

#define BD 4
#define SS 2048
#define DDIM 1024

constexpr size_t NX = (size_t)BD * SS * DDIM;    // 8388608
constexpr size_t NW = (size_t)3 * DDIM * DDIM;   // 3145728
constexpr size_t NP = (size_t)BD * SS * SS;      // 16777216

// Scratch: __device__ globals (module-load allocation, legal under _HX_ENFORCE)
__device__ __nv_bfloat16 g_xh[NX], g_xl[NX];
__device__ __nv_bfloat16 g_wh[NW], g_wl[NW];
__device__ __nv_bfloat16 g_qh[NX], g_ql[NX];
__device__ __nv_bfloat16 g_kh[NX], g_kl[NX];
__device__ __nv_bfloat16 g_vh[NX], g_vl[NX];
__device__ __nv_bfloat16 g_vTh[NX], g_vTl[NX];
__device__ float         g_p [NP];
__device__ __nv_bfloat16 g_ph[NP], g_pl[NP];

// ---------------- tiling ----------------
constexpr int NTHREADS = 512;              // 16 warps -> 4 warps per SMSP
constexpr int CHUNK   = 64;                // K bf16 elems per pipeline chunk
constexpr int TILE_B  = 128 * 128;         // 128 rows x 128B = 16 KB
constexpr int STAGE_B = 4 * TILE_B;        // Ah, Al, Bh, Bl = 64 KB
constexpr int NSTAGE  = 3;                 // 3-stage ring = 192 KB
constexpr int DSMEM   = NSTAGE * STAGE_B;

// ---------------- PTX helpers (all base-sm_103 legal) ----------------
__device__ __forceinline__ uint32_t smem_u32(const void* p) {
    uint32_t a;
    asm("{ .reg .u64 t; cvta.to.shared.u64 t, %1; cvt.u32.u64 %0, t; }"
        : "=r"(a) : "l"(p));
    return a;
}
__device__ __forceinline__ void cpasync16(uint32_t dst, const void* src) {
    asm volatile("cp.async.cg.shared.global [%0], [%1], 16;"
                 :: "r"(dst), "l"(src) : "memory");
}
__device__ __forceinline__ void cp_commit() {
    asm volatile("cp.async.commit_group;" ::: "memory");
}
__device__ __forceinline__ void cp_wait1() {
    asm volatile("cp.async.wait_group 1;" ::: "memory");
}
__device__ __forceinline__ uint32_t swz(uint32_t off) {
    return off ^ ((off >> 3) & 0x70);
}

#define LDSM4(r, a) \
    asm volatile("ldmatrix.sync.aligned.m8n8.x4.shared.b16 {%0,%1,%2,%3}, [%4];" \
        : "=r"((r)[0]), "=r"((r)[1]), "=r"((r)[2]), "=r"((r)[3]) : "r"(a))
#define LDSM2(r, a) \
    asm volatile("ldmatrix.sync.aligned.m8n8.x2.shared.b16 {%0,%1}, [%2];" \
        : "=r"((r)[0]), "=r"((r)[1]) : "r"(a))
#define MMA16816(d, a, b) \
    asm volatile("mma.sync.aligned.m16n8k16.row.col.f32.bf16.bf16.f32 " \
        "{%0,%1,%2,%3}, {%4,%5,%6,%7}, {%8,%9}, {%0,%1,%2,%3};" \
        : "+f"((d)[0]), "+f"((d)[1]), "+f"((d)[2]), "+f"((d)[3]) \
        : "r"((a)[0]), "r"((a)[1]), "r"((a)[2]), "r"((a)[3]), \
          "r"((b)[0]), "r"((b)[1]))

// ---------------- chunk loader: 128 rows x 64 bf16 -> SW128 smem (512 thr) ----
__device__ __forceinline__ void issue_tile(uint32_t sbase,
                                           const __nv_bfloat16* __restrict__ src,
                                           int ld, int r0, int c0) {
    const int t   = threadIdx.x;           // 0..511
    const int row = t >> 2, q = t & 3;     // 128 rows x 4 quarters (32B each)
    const __nv_bfloat16* g = src + (size_t)(r0 + row) * ld + c0 + q * 16;
    const uint32_t off = row * 128 + q * 32;
    cpasync16(sbase + swz(off),      g);
    cpasync16(sbase + swz(off + 16), g + 8);
}

// ---------------- shared mainloop ----------------
// acc[im][in][4] = sum over K of A(m0..m0+127, :) * B(n0..n0+127, :)^T  (bf16x3)
// A,B stored K-major. 16 warps: wm=(wid&3)*32 (im 0..1), wn=(wid>>2)*32 (in 0..3).
// Acc (im,in): rows wm+16*im + lane/4 (+8 for regs 2,3), col wn+8*in+(lane%4)*2.
__device__ void mma_main(const __nv_bfloat16* __restrict__ Ah,
                         const __nv_bfloat16* __restrict__ Al, int lda,
                         const __nv_bfloat16* __restrict__ Bh,
                         const __nv_bfloat16* __restrict__ Bl, int ldb,
                         int m0, int n0, int K, float acc[2][4][4]) {
    extern __shared__ char dsm[];
    const uint32_t sb = smem_u32(dsm);
    const int NC = K / CHUNK;

    auto issue = [&](int c, int s) {
        const uint32_t st = sb + s * STAGE_B;
        const int c0 = c * CHUNK;
        issue_tile(st,              Ah, lda, m0, c0);
        issue_tile(st + TILE_B,     Al, lda, m0, c0);
        issue_tile(st + 2 * TILE_B, Bh, ldb, n0, c0);
        issue_tile(st + 3 * TILE_B, Bl, ldb, n0, c0);
        cp_commit();
    };

    const int lane = threadIdx.x & 31;
    const int wid  = threadIdx.x >> 5;
    const int wm   = (wid & 3) * 32;
    const int wn   = (wid >> 2) * 32;
    const int arow = (lane & 7) + ((lane >> 3) & 1) * 8;  // A ldmatrix row-in-tile16
    const int asel = lane >> 4;                           // A k-unit select
    const int brow = lane & 7;                            // B ldmatrix row
    const int bsel = (lane >> 3) & 1;                     // B k-unit select

    // prologue: fill 2 of 3 stages
    issue(0, 0);
    if (NC > 1) issue(1, 1); else cp_commit();

    int buf = 0;
    for (int c = 0; c < NC; ++c) {
        cp_wait1();            // chunk c resident (<=1 group still in flight)
        __syncthreads();       // all threads see stage `buf`; stage (c+2)%3 free
        if (c + 2 < NC) issue(c + 2, (c + 2) % NSTAGE); else cp_commit();

        const uint32_t st = sb + buf * STAGE_B;
        #pragma unroll
        for (int ks = 0; ks < 4; ++ks) {
            uint32_t ah[2][4], al[2][4], bh[4][2], bl[4][2];
            #pragma unroll
            for (int im = 0; im < 2; ++im) {
                const int R = wm + 16 * im + arow;
                const uint32_t off = R * 128 + (((ks * 2 + asel) ^ (R & 7)) << 4);
                LDSM4(ah[im], st + off);
                LDSM4(al[im], st + TILE_B + off);
            }
            #pragma unroll
            for (int in = 0; in < 4; ++in) {
                const int R = wn + 8 * in + brow;
                const uint32_t off = R * 128 + (((ks * 2 + bsel) ^ (R & 7)) << 4);
                LDSM2(bh[in], st + 2 * TILE_B + off);
                LDSM2(bl[in], st + 3 * TILE_B + off);
            }
            // term-major ordering: 8 independent accumulators per term
            #pragma unroll
            for (int im = 0; im < 2; ++im)
                #pragma unroll
                for (int in = 0; in < 4; ++in)
                    MMA16816(acc[im][in], ah[im], bh[in]);
            #pragma unroll
            for (int im = 0; im < 2; ++im)
                #pragma unroll
                for (int in = 0; in < 4; ++in)
                    MMA16816(acc[im][in], ah[im], bl[in]);
            #pragma unroll
            for (int im = 0; im < 2; ++im)
                #pragma unroll
                for (int in = 0; in < 4; ++in)
                    MMA16816(acc[im][in], al[im], bh[in]);
        }
        buf = (buf + 1 == NSTAGE) ? 0 : buf + 1;
    }
}

// ---------------- GEMM kernels ----------------
__global__ void __launch_bounds__(NTHREADS)
qkv_mma_kernel() {
    const int m0 = blockIdx.y * 128, n0 = blockIdx.x * 128;
    float acc[2][4][4] = {};
    mma_main(g_xh, g_xl, DDIM, g_wh, g_wl, DDIM, m0, n0, DDIM, acc);

    const int lane = threadIdx.x & 31, wid = threadIdx.x >> 5;
    const int wm = (wid & 3) * 32, wn = (wid >> 2) * 32;
    const int r = lane >> 2, cq = (lane & 3) * 2;
    const int nt = n0 >> 10;                 // 0:q 1:k 2:v
    __nv_bfloat16 *dh, *dl;
    if (nt == 0)      { dh = g_qh; dl = g_ql; }
    else if (nt == 1) { dh = g_kh; dl = g_kl; }
    else              { dh = g_vh; dl = g_vl; }

    #pragma unroll
    for (int im = 0; im < 2; ++im)
        #pragma unroll
        for (int in = 0; in < 4; ++in) {
            const int col = (n0 & 1023) + wn + 8 * in + cq;
            #pragma unroll
            for (int h2 = 0; h2 < 2; ++h2) {
                const float f0 = acc[im][in][2 * h2];
                const float f1 = acc[im][in][2 * h2 + 1];
                const size_t off = (size_t)(m0 + wm + 16 * im + r + 8 * h2) * DDIM + col;
                __nv_bfloat16 b0 = __float2bfloat16(f0), b1 = __float2bfloat16(f1);
                __nv_bfloat16 c0 = __float2bfloat16(f0 - __bfloat162float(b0));
                __nv_bfloat16 c1 = __float2bfloat16(f1 - __bfloat162float(b1));
                *(uint32_t*)(dh + off) =
                    (uint32_t)__bfloat16_as_ushort(b0) | ((uint32_t)__bfloat16_as_ushort(b1) << 16);
                *(uint32_t*)(dl + off) =
                    (uint32_t)__bfloat16_as_ushort(c0) | ((uint32_t)__bfloat16_as_ushort(c1) << 16);
            }
        }
}

__global__ void __launch_bounds__(NTHREADS)
score_mma_kernel() {
    const int b = blockIdx.z;
    const int m0 = blockIdx.y * 128, n0 = blockIdx.x * 128;
    const size_t bo = (size_t)b * SS * DDIM;
    float acc[2][4][4] = {};
    mma_main(g_qh + bo, g_ql + bo, DDIM, g_kh + bo, g_kl + bo, DDIM, m0, n0, DDIM, acc);

    const int lane = threadIdx.x & 31, wid = threadIdx.x >> 5;
    const int wm = (wid & 3) * 32, wn = (wid >> 2) * 32;
    const int r = lane >> 2, cq = (lane & 3) * 2;
    #pragma unroll
    for (int im = 0; im < 2; ++im)
        #pragma unroll
        for (int in = 0; in < 4; ++in) {
            const int col = n0 + wn + 8 * in + cq;
            #pragma unroll
            for (int h2 = 0; h2 < 2; ++h2) {
                const size_t off =
                    (size_t)(b * SS + m0 + wm + 16 * im + r + 8 * h2) * SS + col;
                *(float2*)(g_p + off) =
                    make_float2(acc[im][in][2 * h2]     * 0.03125f,
                                acc[im][in][2 * h2 + 1] * 0.03125f);
            }
        }
}

__global__ void __launch_bounds__(NTHREADS)
out_mma_kernel(float* __restrict__ out) {
    const int b = blockIdx.z;
    const int m0 = blockIdx.y * 128, n0 = blockIdx.x * 128;
    const size_t po = (size_t)b * SS * SS;
    const size_t vo = (size_t)b * DDIM * SS;
    float acc[2][4][4] = {};
    mma_main(g_ph + po, g_pl + po, SS, g_vTh + vo, g_vTl + vo, SS, m0, n0, SS, acc);

    const int lane = threadIdx.x & 31, wid = threadIdx.x >> 5;
    const int wm = (wid & 3) * 32, wn = (wid >> 2) * 32;
    const int r = lane >> 2, cq = (lane & 3) * 2;
    #pragma unroll
    for (int im = 0; im < 2; ++im)
        #pragma unroll
        for (int in = 0; in < 4; ++in) {
            const int col = n0 + wn + 8 * in + cq;
            #pragma unroll
            for (int h2 = 0; h2 < 2; ++h2) {
                const size_t off =
                    (size_t)(b * SS + m0 + wm + 16 * im + r + 8 * h2) * DDIM + col;
                *(float2*)(out + off) =
                    make_float2(acc[im][in][2 * h2], acc[im][in][2 * h2 + 1]);
            }
        }
}

// ---------------- fp32 -> (hi, lo) bf16 split ----------------
__global__ void convert_hilo(const float* __restrict__ s,
                             __nv_bfloat16* __restrict__ h,
                             __nv_bfloat16* __restrict__ l) {
    const int i = blockIdx.x * 256 + threadIdx.x;
    float4 v = ((const float4*)s)[i];
    __nv_bfloat16 h0 = __float2bfloat16(v.x), h1 = __float2bfloat16(v.y);
    __nv_bfloat16 h2 = __float2bfloat16(v.z), h3 = __float2bfloat16(v.w);
    __nv_bfloat16 l0 = __float2bfloat16(v.x - __bfloat162float(h0));
    __nv_bfloat16 l1 = __float2bfloat16(v.y - __bfloat162float(h1));
    __nv_bfloat16 l2 = __float2bfloat16(v.z - __bfloat162float(h2));
    __nv_bfloat16 l3 = __float2bfloat16(v.w - __bfloat162float(h3));
    uint2 uh, ul;
    uh.x = (uint32_t)__bfloat16_as_ushort(h0) | ((uint32_t)__bfloat16_as_ushort(h1) << 16);
    uh.y = (uint32_t)__bfloat16_as_ushort(h2) | ((uint32_t)__bfloat16_as_ushort(h3) << 16);
    ul.x = (uint32_t)__bfloat16_as_ushort(l0) | ((uint32_t)__bfloat16_as_ushort(l1) << 16);
    ul.y = (uint32_t)__bfloat16_as_ushort(l2) | ((uint32_t)__bfloat16_as_ushort(l3) << 16);
    ((uint2*)h)[i] = uh;
    ((uint2*)l)[i] = ul;
}

// ---------------- v[b][s][d] -> vT[b][d][s] (bf16) ----------------
__global__ void transpose_v() {
    __shared__ __nv_bfloat16 ts[32][33];
    const int z = blockIdx.z, b = z >> 1;
    const __nv_bfloat16* src = (z & 1) ? g_vl  : g_vh;
    __nv_bfloat16*       dst = (z & 1) ? g_vTl : g_vTh;
    const int s0 = blockIdx.x * 32, d0 = blockIdx.y * 32;
    const int c = threadIdx.x, r = threadIdx.y;
    #pragma unroll
    for (int i = 0; i < 4; ++i) {
        const int rr = r + 8 * i;
        ts[rr][c] = src[(size_t)(b * SS + s0 + rr) * DDIM + d0 + c];
    }
    __syncthreads();
    #pragma unroll
    for (int i = 0; i < 4; ++i) {
        const int rr = r + 8 * i;
        dst[(size_t)(b * DDIM + d0 + rr) * SS + s0 + c] = ts[c][rr];
    }
}

// ---------------- row softmax over g_p rows (len 2048) -> hi/lo bf16 ----------------
__global__ void softmax_kernel() {
    __shared__ float red[8];
    __shared__ float bcast;
    const size_t row = blockIdx.x;
    const float* p = g_p + row * SS;
    const int tid = threadIdx.x;

    float4 a = ((const float4*)p)[tid];
    float4 c = ((const float4*)p)[tid + 256];

    float m = fmaxf(fmaxf(fmaxf(a.x, a.y), fmaxf(a.z, a.w)),
                    fmaxf(fmaxf(c.x, c.y), fmaxf(c.z, c.w)));
    #pragma unroll
    for (int o = 16; o > 0; o >>= 1) m = fmaxf(m, __shfl_xor_sync(~0u, m, o));
    if ((tid & 31) == 0) red[tid >> 5] = m;
    __syncthreads();
    if (tid < 32) {
        float t = (tid < 8) ? red[tid] : -3.4e38f;
        #pragma unroll
        for (int o = 4; o > 0; o >>= 1) t = fmaxf(t, __shfl_xor_sync(~0u, t, o));
        if (tid == 0) bcast = t;
    }
    __syncthreads();
    m = bcast;

    a.x = __expf(a.x - m); a.y = __expf(a.y - m);
    a.z = __expf(a.z - m); a.w = __expf(a.w - m);
    c.x = __expf(c.x - m); c.y = __expf(c.y - m);
    c.z = __expf(c.z - m); c.w = __expf(c.w - m);
    float s = (a.x + a.y) + (a.z + a.w) + (c.x + c.y) + (c.z + c.w);
    #pragma unroll
    for (int o = 16; o > 0; o >>= 1) s += __shfl_xor_sync(~0u, s, o);
    __syncthreads();
    if ((tid & 31) == 0) red[tid >> 5] = s;
    __syncthreads();
    if (tid < 32) {
        float t = (tid < 8) ? red[tid] : 0.0f;
        #pragma unroll
        for (int o = 4; o > 0; o >>= 1) t += __shfl_xor_sync(~0u, t, o);
        if (tid == 0) bcast = t;
    }
    __syncthreads();
    const float inv = 1.0f / bcast;

    a.x *= inv; a.y *= inv; a.z *= inv; a.w *= inv;
    c.x *= inv; c.y *= inv; c.z *= inv; c.w *= inv;

    auto emit = [&](float4 v, size_t col) {
        __nv_bfloat16 h0 = __float2bfloat16(v.x), h1 = __float2bfloat16(v.y);
        __nv_bfloat16 h2 = __float2bfloat16(v.z), h3 = __float2bfloat16(v.w);
        __nv_bfloat16 l0 = __float2bfloat16(v.x - __bfloat162float(h0));
        __nv_bfloat16 l1 = __float2bfloat16(v.y - __bfloat162float(h1));
        __nv_bfloat16 l2 = __float2bfloat16(v.z - __bfloat162float(h2));
        __nv_bfloat16 l3 = __float2bfloat16(v.w - __bfloat162float(h3));
        uint2 uh, ul;
        uh.x = (uint32_t)__bfloat16_as_ushort(h0) | ((uint32_t)__bfloat16_as_ushort(h1) << 16);
        uh.y = (uint32_t)__bfloat16_as_ushort(h2) | ((uint32_t)__bfloat16_as_ushort(h3) << 16);
        ul.x = (uint32_t)__bfloat16_as_ushort(l0) | ((uint32_t)__bfloat16_as_ushort(l1) << 16);
        ul.y = (uint32_t)__bfloat16_as_ushort(l2) | ((uint32_t)__bfloat16_as_ushort(l3) << 16);
        *(uint2*)(g_ph + row * SS + col) = uh;
        *(uint2*)(g_pl + row * SS + col) = ul;
    };
    emit(a, (size_t)tid * 4);
    emit(c, (size_t)tid * 4 + 1024);
}

// ---------------------------------------------------------------------------
extern "C" void kernel_launch(void* const* d_in, const int* in_sizes, int n_in,
                              void* d_out, int out_size) {
    const float* x = (const float*)d_in[0];   // [4, 2048, 1024]
    const float* W = (const float*)d_in[1];   // [3072, 1024]
    float* out = (float*)d_out;               // [4, 2048, 1024]
    (void)in_sizes; (void)n_in; (void)out_size;

    cudaFuncSetAttribute(qkv_mma_kernel,   cudaFuncAttributeMaxDynamicSharedMemorySize, DSMEM);
    cudaFuncSetAttribute(score_mma_kernel, cudaFuncAttributeMaxDynamicSharedMemorySize, DSMEM);
    cudaFuncSetAttribute(out_mma_kernel,   cudaFuncAttributeMaxDynamicSharedMemorySize, DSMEM);

    __nv_bfloat16 *xh, *xl, *wh, *wl;
    cudaGetSymbolAddress((void**)&xh, g_xh);
    cudaGetSymbolAddress((void**)&xl, g_xl);
    cudaGetSymbolAddress((void**)&wh, g_wh);
    cudaGetSymbolAddress((void**)&wl, g_wl);

    convert_hilo<<<(int)(NX / 4 / 256), 256>>>(x, xh, xl);
    convert_hilo<<<(int)(NW / 4 / 256), 256>>>(W, wh, wl);

    qkv_mma_kernel  <<<dim3(3 * DDIM / 128, BD * SS / 128), NTHREADS, DSMEM>>>();
    transpose_v     <<<dim3(SS / 32, DDIM / 32, BD * 2), dim3(32, 8)>>>();
    score_mma_kernel<<<dim3(SS / 128, SS / 128, BD), NTHREADS, DSMEM>>>();
    softmax_kernel  <<<BD * SS, 256>>>();
    out_mma_kernel  <<<dim3(DDIM / 128, SS / 128, BD), NTHREADS, DSMEM>>>(out);
}